// round 12
// baseline (speedup 1.0000x reference)
#include <cuda_runtime.h>

#define BB  64
#define TT  4096
#define HH  1024
#define NHH 4

#define GPB 128                    // GEMV blocks per batch
#define GROUP (GPB + NHH)          // 132 blocks per batch group
#define TOTAL_BLOCKS (BB * GROUP + 1)  // 8449

// Scratch, TRANSPOSED: h[b][n][t] : [B, NH, T] = 4 MB
__device__ float g_h[BB * NHH * TT];
__device__ float g_part[BB * NHH];
__device__ int   g_done[BB];   // GEMV blocks completed per batch
__device__ int   g_scan_done;  // scan blocks completed

__global__ __launch_bounds__(256) void k_fused(const float* __restrict__ x,
                                               const float* __restrict__ W,
                                               const float* __restrict__ bias,
                                               const float* __restrict__ decay,
                                               const float* __restrict__ head_w,
                                               float* __restrict__ out) {
    int bid = blockIdx.x;
    int tid = threadIdx.x;
    int grp = bid / GROUP;       // batch group (grp==BB for the final block)
    int r   = bid - grp * GROUP; // slot within group

    if (grp < BB && r < GPB) {
        // ------------- Phase A: GEMV tile (32 rows of batch grp) -------------
        __shared__ float4 sW[NHH * (HH / 4)];  // 16 KB
        for (int i = tid; i < NHH * (HH / 4); i += 256)
            sW[i] = reinterpret_cast<const float4*>(W)[i];
        __syncthreads();

        const int ROWS = 4;
        int gemv_bid = grp * GPB + r;  // 0..8191, contiguous row mapping
        int warp_global = (gemv_bid * 256 + tid) >> 5;
        int lane = tid & 31;
        long row0 = (long)warp_global * ROWS;

        float acc[ROWS][NHH];
#pragma unroll
        for (int rr = 0; rr < ROWS; rr++)
#pragma unroll
            for (int n = 0; n < NHH; n++) acc[rr][n] = 0.0f;

        const float4* xp = reinterpret_cast<const float4*>(x) + row0 * (HH / 4);

#pragma unroll
        for (int k = 0; k < (HH / 4) / 32; k++) {  // 8 iterations
            int idx = lane + k * 32;
            float4 w0 = sW[0 * (HH / 4) + idx];
            float4 w1 = sW[1 * (HH / 4) + idx];
            float4 w2 = sW[2 * (HH / 4) + idx];
            float4 w3 = sW[3 * (HH / 4) + idx];
#pragma unroll
            for (int rr = 0; rr < ROWS; rr++) {
                float4 xv = xp[(long)rr * (HH / 4) + idx];
                acc[rr][0] += xv.x * w0.x + xv.y * w0.y + xv.z * w0.z + xv.w * w0.w;
                acc[rr][1] += xv.x * w1.x + xv.y * w1.y + xv.z * w1.z + xv.w * w1.w;
                acc[rr][2] += xv.x * w2.x + xv.y * w2.y + xv.z * w2.z + xv.w * w2.w;
                acc[rr][3] += xv.x * w3.x + xv.y * w3.y + xv.z * w3.z + xv.w * w3.w;
            }
        }

#pragma unroll
        for (int rr = 0; rr < ROWS; rr++)
#pragma unroll
            for (int n = 0; n < NHH; n++)
#pragma unroll
                for (int off = 16; off > 0; off >>= 1)
                    acc[rr][n] += __shfl_xor_sync(0xffffffffu, acc[rr][n], off);

        if (lane == 0) {
            float b0 = bias[0], b1 = bias[1], b2 = bias[2], b3 = bias[3];
            int b = (int)(row0 / TT);
            int t = (int)(row0 % TT);  // 4 consecutive t within batch b
            float* plane = g_h + (size_t)b * NHH * TT + t;
            *reinterpret_cast<float4*>(plane + 0 * TT) =
                make_float4(acc[0][0] + b0, acc[1][0] + b0, acc[2][0] + b0, acc[3][0] + b0);
            *reinterpret_cast<float4*>(plane + 1 * TT) =
                make_float4(acc[0][1] + b1, acc[1][1] + b1, acc[2][1] + b1, acc[3][1] + b1);
            *reinterpret_cast<float4*>(plane + 2 * TT) =
                make_float4(acc[0][2] + b2, acc[1][2] + b2, acc[2][2] + b2, acc[3][2] + b2);
            *reinterpret_cast<float4*>(plane + 3 * TT) =
                make_float4(acc[0][3] + b3, acc[1][3] + b3, acc[2][3] + b3, acc[3][3] + b3);
        }

        __syncthreads();
        __threadfence();
        if (tid == 0) atomicAdd(&g_done[grp], 1);

    } else if (grp < BB) {
        // ------- Phase B: EMA scan for (b=grp, n=r-GPB), L2-hot g_h ----------
        int b = grp, n = r - GPB;
        int wid = tid >> 5, lane = tid & 31;

        if (tid == 0)
            while (((volatile int*)g_done)[b] < GPB) {}
        __syncthreads();
        __threadfence();  // acquire

        float d = 1.0f / (1.0f + expf(-decay[n]));
        float od = 1.0f - d;

        const float4* hp4 = reinterpret_cast<const float4*>(
                                g_h + ((size_t)b * NHH + n) * TT) + tid * 4;
        float4 v[4];
#pragma unroll
        for (int i = 0; i < 4; i++) v[i] = hp4[i];

        // Pass 1: local chunk EMA from 0
        float ema = 0.0f;
#pragma unroll
        for (int i = 0; i < 4; i++) {
            ema = d * ema + od * v[i].x;
            ema = d * ema + od * v[i].y;
            ema = d * ema + od * v[i].z;
            ema = d * ema + od * v[i].w;
        }

        float A = d;
#pragma unroll
        for (int s = 0; s < 4; s++) A = A * A;  // d^16

        float a = A, bq = ema;
#pragma unroll
        for (int off = 1; off < 32; off <<= 1) {
            float ap = __shfl_up_sync(0xffffffffu, a, off);
            float bp = __shfl_up_sync(0xffffffffu, bq, off);
            if (lane >= off) { bq = a * bp + bq; a = a * ap; }
        }

        __shared__ float sa[8], sb[8], smax[8];
        if (lane == 31) { sa[wid] = a; sb[wid] = bq; }
        __syncthreads();

        float e_w = 0.0f;
#pragma unroll
        for (int w = 0; w < 8; w++)
            if (w < wid) e_w = sa[w] * e_w + sb[w];

        float a_ex = __shfl_up_sync(0xffffffffu, a, 1);
        float b_ex = __shfl_up_sync(0xffffffffu, bq, 1);
        float e_in = (lane == 0) ? e_w : (a_ex * e_w + b_ex);

        // Pass 2: replay from registers, track max (init 0 per reference)
        ema = e_in;
        float emax = 0.0f;
#pragma unroll
        for (int i = 0; i < 4; i++) {
            ema = d * ema + od * v[i].x; emax = fmaxf(emax, ema);
            ema = d * ema + od * v[i].y; emax = fmaxf(emax, ema);
            ema = d * ema + od * v[i].z; emax = fmaxf(emax, ema);
            ema = d * ema + od * v[i].w; emax = fmaxf(emax, ema);
        }

#pragma unroll
        for (int off = 16; off > 0; off >>= 1)
            emax = fmaxf(emax, __shfl_xor_sync(0xffffffffu, emax, off));
        if (lane == 0) smax[wid] = emax;
        __syncthreads();
        if (tid == 0) {
            float m = smax[0];
#pragma unroll
            for (int w = 1; w < 8; w++) m = fmaxf(m, smax[w]);
            g_part[b * NHH + n] = m;
            __threadfence();
            atomicAdd(&g_scan_done, 1);
        }

    } else {
        // ---------- Phase C: head projection + counter reset ----------------
        if (tid == 0)
            while (*((volatile int*)&g_scan_done) < BB * NHH) {}
        __syncthreads();
        __threadfence();  // acquire

        if (tid < BB) {
            const volatile float* gp = g_part;
            float s = 0.0f;
#pragma unroll
            for (int n = 0; n < NHH; n++)
                s += gp[tid * NHH + n] * head_w[n];
            out[tid] = s;
        }
        __syncthreads();
        if (tid < BB) g_done[tid] = 0;
        if (tid == BB) g_scan_done = 0;
    }
}

extern "C" void kernel_launch(void* const* d_in, const int* in_sizes, int n_in,
                              void* d_out, int out_size) {
    const float* x      = (const float*)d_in[0];
    const float* W      = (const float*)d_in[1];
    const float* bias   = (const float*)d_in[2];
    const float* decay  = (const float*)d_in[3];
    const float* head_w = (const float*)d_in[4];
    float* out = (float*)d_out;

    k_fused<<<TOTAL_BLOCKS, 256>>>(x, W, bias, decay, head_w, out);
}

// round 13
// speedup vs baseline: 1.1905x; 1.1905x over previous
#include <cuda_runtime.h>

#define BB  64
#define TT  4096
#define HH  1024
#define NHH 4

// Scratch, TRANSPOSED: h[b][n][t] : [B, NH, T] = 4 MB
__device__ float g_h[BB * NHH * TT];
__device__ float g_part[BB * NHH];
__device__ int   g_cnt;  // scan-block completion counter (reset in-kernel)

// ---------------------------------------------------------------------------
// Kernel 1: tall-skinny GEMV — unchanged R11 structure (one-shot 8192 blocks,
// 8 warps x 4 rows, W staged in smem, natural regs, transposed stores).
// ---------------------------------------------------------------------------
__global__ __launch_bounds__(256) void k_gemv(const float* __restrict__ x,
                                              const float* __restrict__ W,
                                              const float* __restrict__ bias) {
    __shared__ float4 sW[NHH * (HH / 4)];  // 16 KB
    for (int i = threadIdx.x; i < NHH * (HH / 4); i += 256)
        sW[i] = reinterpret_cast<const float4*>(W)[i];
    __syncthreads();

    const int ROWS = 4;
    int warp_global = (blockIdx.x * 256 + threadIdx.x) >> 5;
    int lane = threadIdx.x & 31;
    long row0 = (long)warp_global * ROWS;

    float acc[ROWS][NHH];
#pragma unroll
    for (int r = 0; r < ROWS; r++)
#pragma unroll
        for (int n = 0; n < NHH; n++) acc[r][n] = 0.0f;

    const float4* xp = reinterpret_cast<const float4*>(x) + row0 * (HH / 4);

#pragma unroll
    for (int k = 0; k < (HH / 4) / 32; k++) {  // 8 iterations
        int idx = lane + k * 32;
        float4 w0 = sW[0 * (HH / 4) + idx];
        float4 w1 = sW[1 * (HH / 4) + idx];
        float4 w2 = sW[2 * (HH / 4) + idx];
        float4 w3 = sW[3 * (HH / 4) + idx];
#pragma unroll
        for (int r = 0; r < ROWS; r++) {
            float4 xv = xp[(long)r * (HH / 4) + idx];
            acc[r][0] += xv.x * w0.x + xv.y * w0.y + xv.z * w0.z + xv.w * w0.w;
            acc[r][1] += xv.x * w1.x + xv.y * w1.y + xv.z * w1.z + xv.w * w1.w;
            acc[r][2] += xv.x * w2.x + xv.y * w2.y + xv.z * w2.z + xv.w * w2.w;
            acc[r][3] += xv.x * w3.x + xv.y * w3.y + xv.z * w3.z + xv.w * w3.w;
        }
    }

#pragma unroll
    for (int r = 0; r < ROWS; r++)
#pragma unroll
        for (int n = 0; n < NHH; n++)
#pragma unroll
            for (int off = 16; off > 0; off >>= 1)
                acc[r][n] += __shfl_xor_sync(0xffffffffu, acc[r][n], off);

    if (lane == 0) {
        float b0 = bias[0], b1 = bias[1], b2 = bias[2], b3 = bias[3];
        int b = (int)(row0 / TT);
        int t = (int)(row0 % TT);  // 4 consecutive t, same batch
        float* plane = g_h + (size_t)b * NHH * TT + t;
        *reinterpret_cast<float4*>(plane + 0 * TT) =
            make_float4(acc[0][0] + b0, acc[1][0] + b0, acc[2][0] + b0, acc[3][0] + b0);
        *reinterpret_cast<float4*>(plane + 1 * TT) =
            make_float4(acc[0][1] + b1, acc[1][1] + b1, acc[2][1] + b1, acc[3][1] + b1);
        *reinterpret_cast<float4*>(plane + 2 * TT) =
            make_float4(acc[0][2] + b2, acc[1][2] + b2, acc[2][2] + b2, acc[3][2] + b2);
        *reinterpret_cast<float4*>(plane + 3 * TT) =
            make_float4(acc[0][3] + b3, acc[1][3] + b3, acc[2][3] + b3, acc[3][3] + b3);
    }
}

// ---------------------------------------------------------------------------
// Kernel 2: EMA scan + max, 1024 threads/block, grid (B, NH). Each thread
// owns a 4-step chunk (one float4) -> whole 4 MB requested in one burst.
// Two-level affine scan: warp KS + warp-0 KS over the 32 warp aggregates.
// Last block (atomic counter) does the head projection.
// ---------------------------------------------------------------------------
__global__ __launch_bounds__(1024) void k_scan(const float* __restrict__ decay,
                                               const float* __restrict__ head_w,
                                               float* __restrict__ out) {
    int b = blockIdx.x, n = blockIdx.y;
    int tid = threadIdx.x;
    int wid = tid >> 5, lane = tid & 31;

    float d = 1.0f / (1.0f + expf(-decay[n]));
    float od = 1.0f - d;

    // One float4 (4 consecutive t) per thread — fully coalesced, max MLP
    float4 v = reinterpret_cast<const float4*>(
                   g_h + ((size_t)b * NHH + n) * TT)[tid];

    // Local 4-step EMA from 0
    float ema = od * v.x;
    ema = d * ema + od * v.y;
    ema = d * ema + od * v.z;
    ema = d * ema + od * v.w;

    float d2 = d * d;
    float A = d2 * d2;  // d^4

    // Warp inclusive KS scan of affine maps (a,bq): e -> a*e + bq
    float a = A, bq = ema;
#pragma unroll
    for (int off = 1; off < 32; off <<= 1) {
        float ap = __shfl_up_sync(0xffffffffu, a, off);
        float bp = __shfl_up_sync(0xffffffffu, bq, off);
        if (lane >= off) { bq = a * bp + bq; a = a * ap; }
    }

    __shared__ float sa[32], sb[32], smax[32];
    __shared__ int s_last;
    if (lane == 31) { sa[wid] = a; sb[wid] = bq; }
    __syncthreads();

    // Warp 0: inclusive KS over the 32 warp aggregates
    if (wid == 0) {
        float wa = sa[lane], wb = sb[lane];
#pragma unroll
        for (int off = 1; off < 32; off <<= 1) {
            float ap = __shfl_up_sync(0xffffffffu, wa, off);
            float bp = __shfl_up_sync(0xffffffffu, wb, off);
            if (lane >= off) { wb = wa * bp + wb; wa = wa * ap; }
        }
        sb[lane] = wb;  // inclusive warp-prefix offsets (a not needed further)
    }
    __syncthreads();

    // Incoming state for this thread = exclusive(lane) ∘ exclusive(warp)
    float e_w = (wid == 0) ? 0.0f : sb[wid - 1];
    float a_ex = __shfl_up_sync(0xffffffffu, a, 1);
    float b_ex = __shfl_up_sync(0xffffffffu, bq, 1);
    float e_in = (lane == 0) ? e_w : (a_ex * e_w + b_ex);

    // Replay 4 steps with incoming state, track max (init 0 per reference)
    ema = d * e_in + od * v.x;
    float emax = fmaxf(0.0f, ema);
    ema = d * ema + od * v.y; emax = fmaxf(emax, ema);
    ema = d * ema + od * v.z; emax = fmaxf(emax, ema);
    ema = d * ema + od * v.w; emax = fmaxf(emax, ema);

#pragma unroll
    for (int off = 16; off > 0; off >>= 1)
        emax = fmaxf(emax, __shfl_xor_sync(0xffffffffu, emax, off));
    if (lane == 0) smax[wid] = emax;
    __syncthreads();

    if (tid == 0) {
        float m = smax[0];
#pragma unroll
        for (int w = 1; w < 32; w++) m = fmaxf(m, smax[w]);
        g_part[b * NHH + n] = m;
        __threadfence();  // release g_part before counter bump
        int prev = atomicAdd(&g_cnt, 1);
        s_last = (prev == BB * NHH - 1);
    }
    __syncthreads();

    // Last finishing block: projection + counter reset for graph replay
    if (s_last) {
        __threadfence();  // acquire
        if (tid < BB) {
            const volatile float* gp = g_part;
            float s = 0.0f;
#pragma unroll
            for (int nn = 0; nn < NHH; nn++)
                s += gp[tid * NHH + nn] * head_w[nn];
            out[tid] = s;
        }
        __syncthreads();
        if (tid == 0) g_cnt = 0;
    }
}

// ---------------------------------------------------------------------------
extern "C" void kernel_launch(void* const* d_in, const int* in_sizes, int n_in,
                              void* d_out, int out_size) {
    const float* x      = (const float*)d_in[0];
    const float* W      = (const float*)d_in[1];
    const float* bias   = (const float*)d_in[2];
    const float* decay  = (const float*)d_in[3];
    const float* head_w = (const float*)d_in[4];
    float* out = (float*)d_out;

    int blocks = (BB * TT) / (4 * 8);  // 8192
    k_gemv<<<blocks, 256>>>(x, W, bias);
    dim3 sg(BB, NHH);
    k_scan<<<sg, 1024>>>(decay, head_w, out);
}